// round 9
// baseline (speedup 1.0000x reference)
#include <cuda_runtime.h>
#include <cuda_bf16.h>

// TD(lambda) backward scan — warp-per-row, 4-elem micro-segments + warp scan.
// R6: v_next staged via cp.async (no LDG->reg->STS round trip, lower reg
// pressure -> +occupancy), streaming cache hints on the use-once streams.
//
// ret_t = a_t*ret_{t+1} + b_t;  a_t = gamma*(1-d_t)*lam_t,
//                               b_t = r_t + gamma*(1-d_t)*(1-lam_t)*v_{t+1}

#define B_TOT 32768
#define S_LEN 512
#define EPS_F 1e-8f

static constexpr int WPB = 8;   // warps (rows) per block -> 256 threads

__device__ __forceinline__ void cp_async4(void* smem_dst, const void* gmem_src) {
    unsigned sa = (unsigned)__cvta_generic_to_shared(smem_dst);
    asm volatile("cp.async.ca.shared.global [%0], [%1], 4;\n"
                 :: "r"(sa), "l"(gmem_src) : "memory");
}
__device__ __forceinline__ void cp_async_commit_wait() {
    asm volatile("cp.async.commit_group;\n"
                 "cp.async.wait_group 0;\n" ::: "memory");
}

__device__ __forceinline__ float4 ldcs4(const float* p) {
    return __ldcs((const float4*)p);
}

__global__ __launch_bounds__(WPB * 32)
void gamma_lambda_wscan2_kernel(
    const float* __restrict__ values,    // [B, S+1]
    const float* __restrict__ rewards,   // [B, S]
    const float* __restrict__ dones,     // [B, S]
    const float* __restrict__ raw_gamma, // [1]
    const float* __restrict__ raw_lambd, // [S]
    float* __restrict__ out)             // [B, S]
{
    __shared__ __align__(16) float s_lam[S_LEN];
    __shared__ __align__(16) float s_v[WPB][S_LEN];  // v_next per warp (shifted)
    __shared__ float s_gamma;

    const int tid  = threadIdx.x;
    const int lane = tid & 31;
    const int wid  = tid >> 5;

    const int row = blockIdx.x * WPB + wid;          // exact: 4096*8 = 32768
    const float* vrow = values  + (size_t)row * (S_LEN + 1);
    const float* rrow = rewards + (size_t)row * S_LEN;
    const float* drow = dones   + (size_t)row * S_LEN;
    float*       orow = out     + (size_t)row * S_LEN;

    // ---- stage v_next shifted via cp.async: s_v[i] = values[row, i+1] ----
    float* __restrict__ wv = s_v[wid];
#pragma unroll
    for (int k = 0; k < 16; k++)
        cp_async4(wv + k * 32 + lane, vrow + 1 + k * 32 + lane);

    // overlap: lambda table (tanh) while cp.async bytes are in flight
    for (int i = tid; i < S_LEN; i += WPB * 32)
        s_lam[i] = fmaxf(tanhf(raw_lambd[i]), EPS_F);
    if (tid == 0) s_gamma = fmaxf(tanhf(raw_gamma[0]), EPS_F);

    cp_async_commit_wait();
    __syncthreads();   // covers s_lam, s_gamma, s_v

    const float gamma = s_gamma;

    // ---- per-chunk: coalesced streaming loads, build (a,b), compose ----
    float a[4][4], b[4][4];
    float A[4], Bv[4];
#pragma unroll
    for (int c = 0; c < 4; c++) {
        const int base = c * 128 + lane * 4;
        const float4 r4 = ldcs4(rrow + base);
        const float4 d4 = ldcs4(drow + base);
        const float4 v4 = *(const float4*)(wv    + base);   // LDS.128
        const float4 l4 = *(const float4*)(s_lam + base);
        const float rr[4] = {r4.x, r4.y, r4.z, r4.w};
        const float dd[4] = {d4.x, d4.y, d4.z, d4.w};
        const float vv[4] = {v4.x, v4.y, v4.z, v4.w};
        const float ll[4] = {l4.x, l4.y, l4.z, l4.w};
        float Ac = 1.0f, Bc = 0.0f;
#pragma unroll
        for (int j = 3; j >= 0; --j) {
            const float gd = gamma - gamma * dd[j];          // gamma*(1-d)
            const float aj = gd * ll[j];
            const float bj = fmaf(gd - aj, vv[j], rr[j]);    // r + gd*(1-lam)*v
            a[c][j] = aj; b[c][j] = bj;
            Bc = fmaf(aj, Bc, bj);
            Ac = aj * Ac;
        }
        A[c] = Ac; Bv[c] = Bc;
    }

    // ---- 4 independent warp suffix-inclusive scans ----
#pragma unroll
    for (int off = 1; off < 32; off <<= 1) {
#pragma unroll
        for (int c = 0; c < 4; c++) {
            const float A2 = __shfl_down_sync(0xFFFFFFFFu, A[c],  off);
            const float B2 = __shfl_down_sync(0xFFFFFFFFu, Bv[c], off);
            if (lane + off < 32) {
                Bv[c] = fmaf(A[c], B2, Bv[c]);
                A[c]  = A[c] * A2;
            }
        }
    }

    // chunk totals (lane 0 holds full-chunk map)
    float TA[4], TB[4];
#pragma unroll
    for (int c = 0; c < 4; c++) {
        TA[c] = __shfl_sync(0xFFFFFFFFu, A[c],  0);
        TB[c] = __shfl_sync(0xFFFFFFFFu, Bv[c], 0);
    }

    // exclusive per-lane suffix within each chunk
    float Ae[4], Be[4];
#pragma unroll
    for (int c = 0; c < 4; c++) {
        Ae[c] = __shfl_down_sync(0xFFFFFFFFu, A[c],  1);
        Be[c] = __shfl_down_sync(0xFFFFFFFFu, Bv[c], 1);
        if (lane == 31) { Ae[c] = 1.0f; Be[c] = 0.0f; }
    }

    // ---- chunk boundaries: x[c] = ret_{128(c+1)}; x[3] = values[b,S] ----
    const float v_init = wv[S_LEN - 1];
    float x[4];
    x[3] = v_init;
    x[2] = fmaf(TA[3], x[3], TB[3]);
    x[1] = fmaf(TA[2], x[2], TB[2]);
    x[0] = fmaf(TA[1], x[1], TB[1]);

    // ---- replay, streaming coalesced float4 stores ----
#pragma unroll
    for (int c = 0; c < 4; c++) {
        const float y  = fmaf(Ae[c], x[c], Be[c]);
        const float o3 = fmaf(a[c][3], y,  b[c][3]);
        const float o2 = fmaf(a[c][2], o3, b[c][2]);
        const float o1 = fmaf(a[c][1], o2, b[c][1]);
        const float o0 = fmaf(a[c][0], o1, b[c][0]);
        __stcs((float4*)(orow + c * 128 + lane * 4),
               make_float4(o0, o1, o2, o3));
    }
}

extern "C" void kernel_launch(void* const* d_in, const int* in_sizes, int n_in,
                              void* d_out, int out_size)
{
    const float* values    = (const float*)d_in[0];
    const float* rewards   = (const float*)d_in[1];
    const float* dones     = (const float*)d_in[2];
    const float* raw_gamma = (const float*)d_in[3];
    const float* raw_lambd = (const float*)d_in[4];
    float* out = (float*)d_out;

    const int threads = WPB * 32;          // 256
    const int blocks  = B_TOT / WPB;       // 4096
    gamma_lambda_wscan2_kernel<<<blocks, threads>>>(values, rewards, dones,
                                                    raw_gamma, raw_lambd, out);
}